// round 1
// baseline (speedup 1.0000x reference)
#include <cuda_runtime.h>
#include <math.h>

// Problem constants
#define B_   16
#define C_   64
#define H_   224
#define W_   224
#define HW_  (H_ * W_)          // 50176
#define CHW_ (C_ * HW_)         // 3211264
#define HW4_ (HW_ / 4)          // 12544

// Scratch (device globals — no allocation allowed)
__device__ float g_avg[B_ * HW_];   // 3.2 MB
__device__ float g_max[B_ * HW_];   // 3.2 MB
__device__ float g_gate[B_ * HW_];  // 3.2 MB (post-sigmoid)

// ---------------------------------------------------------------------------
// Kernel 1: channel-wise mean + max reduce.  One thread = 4 consecutive w.
// Reads 205.5 MB, writes 6.4 MB.  Fully coalesced 128B per warp per channel.
// ---------------------------------------------------------------------------
__global__ void reduce_kernel(const float* __restrict__ x) {
    int idx = blockIdx.x * blockDim.x + threadIdx.x;   // float4 index in [0, B*HW/4)
    if (idx >= B_ * HW4_) return;
    int b = idx / HW4_;
    int p = idx - b * HW4_;

    const float4* x4 = (const float4*)x;
    long base = (long)b * (CHW_ / 4) + p;

    float4 s = make_float4(0.f, 0.f, 0.f, 0.f);
    float4 m = make_float4(-INFINITY, -INFINITY, -INFINITY, -INFINITY);

#pragma unroll 8
    for (int c = 0; c < C_; c++) {
        float4 v = x4[base + (long)c * HW4_];
        s.x += v.x; s.y += v.y; s.z += v.z; s.w += v.w;
        m.x = fmaxf(m.x, v.x); m.y = fmaxf(m.y, v.y);
        m.z = fmaxf(m.z, v.z); m.w = fmaxf(m.w, v.w);
    }
    const float inv = 1.0f / (float)C_;
    s.x *= inv; s.y *= inv; s.z *= inv; s.w *= inv;

    ((float4*)g_avg)[idx] = s;
    ((float4*)g_max)[idx] = m;
}

// ---------------------------------------------------------------------------
// Kernel 2: 7x7 conv (2ch -> 1ch, pad 3) + bias + sigmoid.
// 32x8 block computes a 32x8 output tile from a (38 x 14 x 2) smem halo tile.
// ---------------------------------------------------------------------------
#define TW 38          // 32 + 6
#define TH 14          // 8 + 6
#define TWP 40         // padded row

__global__ void conv_sigmoid_kernel(const float* __restrict__ conv_w,
                                    const float* __restrict__ conv_b) {
    __shared__ float s_tile[2][TH][TWP];
    __shared__ float s_w[98];

    int tx = threadIdx.x;              // 0..31
    int ty = threadIdx.y;              // 0..7
    int tid = ty * 32 + tx;            // 0..255

    int w0 = blockIdx.x * 32;          // 7 blocks
    int h0 = blockIdx.y * 8;           // 28 blocks
    int b  = blockIdx.z;               // 16

    if (tid < 98) s_w[tid] = conv_w[tid];

    // cooperative halo load: 2 * 14 * 38 = 1064 elements
    const float* src[2] = { g_avg + b * HW_, g_max + b * HW_ };
    for (int i = tid; i < 2 * TH * TW; i += 256) {
        int ch = i / (TH * TW);
        int r  = (i - ch * TH * TW) / TW;
        int cc = i - ch * TH * TW - r * TW;
        int gh = h0 + r - 3;
        int gw = w0 + cc - 3;
        float v = 0.f;
        if (gh >= 0 && gh < H_ && gw >= 0 && gw < W_)
            v = src[ch][gh * W_ + gw];
        s_tile[ch][r][cc] = v;
    }
    __syncthreads();

    float acc = conv_b[0];
#pragma unroll
    for (int ch = 0; ch < 2; ch++)
#pragma unroll
        for (int kh = 0; kh < 7; kh++)
#pragma unroll
            for (int kw = 0; kw < 7; kw++)
                acc = fmaf(s_tile[ch][ty + kh][tx + kw],
                           s_w[ch * 49 + kh * 7 + kw], acc);

    float gate = 1.0f / (1.0f + __expf(-acc));
    g_gate[b * HW_ + (h0 + ty) * W_ + (w0 + tx)] = gate;
}

// ---------------------------------------------------------------------------
// Kernel 3: out = x * gate (gate broadcast over channels).  Pure bandwidth.
// ---------------------------------------------------------------------------
__global__ void gate_mul_kernel(const float* __restrict__ x,
                                float* __restrict__ out) {
    long idx4 = (long)blockIdx.x * blockDim.x + threadIdx.x;
    const long total4 = (long)B_ * CHW_ / 4;   // 12,845,056
    if (idx4 >= total4) return;

    long fidx = idx4 * 4;
    int b  = (int)(fidx / CHW_);
    int rem = (int)(fidx - (long)b * CHW_);
    int hw = rem % HW_;                        // divisible by 4

    float4 g = ((const float4*)g_gate)[b * HW4_ + (hw >> 2)];
    float4 v = ((const float4*)x)[idx4];
    v.x *= g.x; v.y *= g.y; v.z *= g.z; v.w *= g.w;
    ((float4*)out)[idx4] = v;
}

// ---------------------------------------------------------------------------
extern "C" void kernel_launch(void* const* d_in, const int* in_sizes, int n_in,
                              void* d_out, int out_size) {
    const float* x      = (const float*)d_in[0];
    const float* conv_w = (const float*)d_in[1];
    const float* conv_b = (const float*)d_in[2];
    float* out = (float*)d_out;

    // K1: reduce over channels
    {
        int n = B_ * HW4_;                   // 200704 threads
        reduce_kernel<<<(n + 255) / 256, 256>>>(x);
    }
    // K2: conv + sigmoid -> gate
    {
        dim3 blk(32, 8);
        dim3 grd(W_ / 32, H_ / 8, B_);       // 7 x 28 x 16
        conv_sigmoid_kernel<<<grd, blk>>>(conv_w, conv_b);
    }
    // K3: broadcast multiply
    {
        long n = (long)B_ * CHW_ / 4;
        gate_mul_kernel<<<(int)((n + 255) / 256), 256>>>(x, out);
    }
}